// round 1
// baseline (speedup 1.0000x reference)
#include <cuda_runtime.h>
#include <math.h>

#define NB 16
#define HH 32
#define WW 32
#define TT 16
#define VV 64
#define PP (HH*WW)          // 1024
#define LRELU_ALPHA 0.2f

// ---------------- scratch (device globals; no runtime allocation) ----------
__device__ float g_Wt[(size_t)NB*TT*PP*VV];   // [n][t][p][v]  64 MB
__device__ float g_Ei[NB*VV*TT];
__device__ float g_Ej[NB*VV*TT];
__device__ float g_att[NB*TT*VV*VV];          // [n][t][i][j]  4 MB
__device__ float g_adjn[VV*VV];
__device__ float g_M[NB*TT*VV*VV];            // [n][t][j][v]  4 MB

// ---------------- 1) 3x3 SAME conv, per (n,v) image, channels T ------------
// Wh[n,v,y,x,to] = b[to] + sum_{dy,dx,ti} h[n,y+dy-1,x+dx-1,ti,v]*w[dy,dx,ti,to]
// write to g_Wt[n][to][p][v]
__global__ void __launch_bounds__(128) k_conv(const float* __restrict__ h,
                                              const float* __restrict__ cw,
                                              const float* __restrict__ cb) {
    __shared__ float sw[9*TT*TT];   // 2304 floats
    __shared__ float sb[TT];
    for (int i = threadIdx.x; i < 9*TT*TT; i += 128) sw[i] = cw[i];
    if (threadIdx.x < TT) sb[threadIdx.x] = cb[threadIdx.x];
    __syncthreads();

    const int v = threadIdx.x & 63;
    const int x = (blockIdx.x << 1) | (threadIdx.x >> 6);
    const int y = blockIdx.y;
    const int n = blockIdx.z;

    float acc[TT];
#pragma unroll
    for (int t = 0; t < TT; t++) acc[t] = sb[t];

    for (int dy = 0; dy < 3; dy++) {
        const int yy = y + dy - 1;
        if (yy < 0 || yy >= HH) continue;
        for (int dx = 0; dx < 3; dx++) {
            const int xx = x + dx - 1;
            if (xx < 0 || xx >= WW) continue;
            const float* hp = h + ((size_t)((n*HH + yy)*WW + xx) * TT) * VV + v;
            const float* wp = sw + (dy*3 + dx) * TT * TT;
#pragma unroll
            for (int ti = 0; ti < TT; ti++) {
                const float hv = hp[ti * VV];
#pragma unroll
                for (int to = 0; to < TT; to++)
                    acc[to] += hv * wp[ti*TT + to];
            }
        }
    }
    const int p = y*WW + x;
#pragma unroll
    for (int t = 0; t < TT; t++)
        g_Wt[((size_t)(n*TT + t) * PP + p) * VV + v] = acc[t];
}

// ---------------- 2) Ei / Ej reductions ------------------------------------
// Ei[n,v,tp] = sum_{t<16, rw<64} Wt[n][t][2*tp*32 + rw][v] * a[(rw)*16 + t]      (rw=r*32+w -> a idx (r*64+w)*16+t)
// Ej same with a[(r*64+32+w)*16+t]
__global__ void __launch_bounds__(256) k_eij(const float* __restrict__ a) {
    __shared__ float sa[2*HH*WW];          // 2048
    __shared__ float red[2][4][VV];
    for (int i = threadIdx.x; i < 2*HH*WW; i += 256) sa[i] = a[i];
    __syncthreads();

    const int v  = threadIdx.x & 63;
    const int q  = threadIdx.x >> 6;       // 0..3, splits t range
    const int tp = blockIdx.x;             // 0..15
    const int n  = blockIdx.y;

    float ei = 0.f, ej = 0.f;
    for (int t = q*4; t < q*4 + 4; t++) {
        const float* wt = g_Wt + ((size_t)(n*TT + t) * PP + 2*tp*WW) * VV + v;
#pragma unroll 8
        for (int rw = 0; rw < 64; rw++) {   // p offset within the 2 rows
            const float xv = wt[rw * VV];
            const int r = rw >> 5, w = rw & 31;
            ei += xv * sa[(r*64 + w)      * 16 + t];
            ej += xv * sa[(r*64 + 32 + w) * 16 + t];
        }
    }
    red[0][q][v] = ei; red[1][q][v] = ej;
    __syncthreads();
    if (q == 0) {
        float si = red[0][0][v] + red[0][1][v] + red[0][2][v] + red[0][3][v];
        float sj = red[1][0][v] + red[1][1][v] + red[1][2][v] + red[1][3][v];
        g_Ei[(n*VV + v)*TT + tp] = si;
        g_Ej[(n*VV + v)*TT + tp] = sj;
    }
}

// ---------------- 3) adjacency normalization (tiny, 1 block) ---------------
__global__ void __launch_bounds__(64) k_adj(const float* __restrict__ B) {
    __shared__ float smin[VV], smax[VV], sd[VV];
    __shared__ float s_amin, s_ascale;
    const int i = threadIdx.x;
    float mn = 1e30f, mx = -1e30f;
    for (int j = 0; j < VV; j++) {
        float val = B[i*VV + j] + (i == j ? 1.f : 0.f);
        mn = fminf(mn, val); mx = fmaxf(mx, val);
    }
    smin[i] = mn; smax[i] = mx;
    __syncthreads();
    if (i == 0) {
        float a = 1e30f, b = -1e30f;
        for (int j = 0; j < VV; j++) { a = fminf(a, smin[j]); b = fmaxf(b, smax[j]); }
        s_amin = a; s_ascale = 1.f / (b - a);
    }
    __syncthreads();
    const float amin = s_amin, asc = s_ascale;
    float rs = 0.f;
    for (int j = 0; j < VV; j++)
        rs += (B[i*VV + j] + (i == j ? 1.f : 0.f) - amin) * asc;
    sd[i] = 1.f / sqrtf(rs);
    __syncthreads();
    const float di = sd[i];
    for (int j = 0; j < VV; j++) {
        float val = (B[i*VV + j] + (i == j ? 1.f : 0.f) - amin) * asc;
        g_adjn[i*VV + j] = val * di * sd[j];
    }
}

// ---------------- 4) leaky-relu + softmax over T ---------------------------
// att[n][t][i][j] = softmax_t( lrelu(Ei[n,i,t] + Ej[n,j,t]) )
__global__ void __launch_bounds__(64) k_soft() {
    const int j = threadIdx.x;
    const int i = blockIdx.x;
    const int n = blockIdx.y;
    __shared__ float sEi[TT];
    if (j < TT) sEi[j] = g_Ei[(n*VV + i)*TT + j];
    __syncthreads();

    float e[TT];
    float mx = -1e30f;
#pragma unroll
    for (int t = 0; t < TT; t++) {
        float x = sEi[t] + g_Ej[(n*VV + j)*TT + t];
        x = (x > 0.f) ? x : LRELU_ALPHA * x;
        e[t] = x;
        mx = fmaxf(mx, x);
    }
    float s = 0.f;
#pragma unroll
    for (int t = 0; t < TT; t++) { e[t] = expf(e[t] - mx); s += e[t]; }
    const float inv = 1.f / s;
#pragma unroll
    for (int t = 0; t < TT; t++)
        g_att[((size_t)(n*TT + t)*VV + i)*VV + j] = e[t] * inv;
}

// ---------------- 5) M[n,t,j,v] = sum_i att[n,t,i,j] * adjn[i,v] -----------
__global__ void __launch_bounds__(256) k_M() {
    const int t = blockIdx.x, n = blockIdx.y;
    __shared__ float s_att[VV*VV];
    __shared__ float s_adj[VV*VV];
    const float* ap = g_att + (size_t)(n*TT + t) * VV * VV;
    for (int idx = threadIdx.x; idx < VV*VV; idx += 256) {
        s_att[idx] = ap[idx];
        s_adj[idx] = g_adjn[idx];
    }
    __syncthreads();
    const int v = threadIdx.x & 63, jg = threadIdx.x >> 6;
    float* mp = g_M + (size_t)(n*TT + t) * VV * VV;
    for (int j = jg*16; j < jg*16 + 16; j++) {
        float acc = 0.f;
#pragma unroll
        for (int i = 0; i < VV; i++)
            acc += s_att[i*VV + j] * s_adj[i*VV + v];
        mp[j*VV + v] = acc;
    }
}

// ---------------- 6) out[n,p,t,v] = elu( sum_j Wt[n,t,p,j] * M[n,t,j,v] ) --
__global__ void __launch_bounds__(256) k_out(float* __restrict__ out) {
    const int pt = blockIdx.x;          // 16 tiles of 64 p-rows
    const int t  = blockIdx.y;
    const int n  = blockIdx.z;
    __shared__ float sA[64*68];         // [j][p], padded
    __shared__ float sM[64*64];         // [j][v]
    const float* wp = g_Wt + ((size_t)(n*TT + t) * PP + pt*64) * VV;
    const float* mp = g_M  + (size_t)(n*TT + t) * VV * VV;
    for (int idx = threadIdx.x; idx < 4096; idx += 256) {
        const int p = idx >> 6, j = idx & 63;
        sA[j*68 + p] = wp[idx];         // transpose into [j][p]
        sM[idx]      = mp[idx];
    }
    __syncthreads();

    const int tv = threadIdx.x & 15, tp = threadIdx.x >> 4;
    const int v0 = tv * 4, p0 = tp * 4;
    float acc[4][4] = {};
#pragma unroll
    for (int j = 0; j < 64; j++) {
        const float4 a4 = *(const float4*)&sA[j*68 + p0];
        const float4 b4 = *(const float4*)&sM[j*64 + v0];
        acc[0][0] += a4.x*b4.x; acc[0][1] += a4.x*b4.y; acc[0][2] += a4.x*b4.z; acc[0][3] += a4.x*b4.w;
        acc[1][0] += a4.y*b4.x; acc[1][1] += a4.y*b4.y; acc[1][2] += a4.y*b4.z; acc[1][3] += a4.y*b4.w;
        acc[2][0] += a4.z*b4.x; acc[2][1] += a4.z*b4.y; acc[2][2] += a4.z*b4.z; acc[2][3] += a4.z*b4.w;
        acc[3][0] += a4.w*b4.x; acc[3][1] += a4.w*b4.y; acc[3][2] += a4.w*b4.z; acc[3][3] += a4.w*b4.w;
    }
#pragma unroll
    for (int pi = 0; pi < 4; pi++) {
        float4 w4;
        float x0 = acc[pi][0], x1 = acc[pi][1], x2 = acc[pi][2], x3 = acc[pi][3];
        w4.x = (x0 > 0.f) ? x0 : expm1f(x0);
        w4.y = (x1 > 0.f) ? x1 : expm1f(x1);
        w4.z = (x2 > 0.f) ? x2 : expm1f(x2);
        w4.w = (x3 > 0.f) ? x3 : expm1f(x3);
        *(float4*)(out + (((size_t)(n*PP + pt*64 + p0 + pi)) * TT + t) * VV + v0) = w4;
    }
}

// ---------------------------------------------------------------------------
extern "C" void kernel_launch(void* const* d_in, const int* in_sizes, int n_in,
                              void* d_out, int out_size) {
    const float* h  = (const float*)d_in[0];   // (16,32,32,16,64)
    const float* cw = (const float*)d_in[1];   // (3,3,16,16)
    const float* cb = (const float*)d_in[2];   // (16,)
    const float* a  = (const float*)d_in[3];   // (2048,1)
    const float* B  = (const float*)d_in[4];   // (64,64)
    float* out = (float*)d_out;

    k_conv<<<dim3(WW/2, HH, NB), 128>>>(h, cw, cb);
    k_adj<<<1, 64>>>(B);
    k_eij<<<dim3(TT, NB), 256>>>(a);
    k_soft<<<dim3(VV, NB), 64>>>();
    k_M<<<dim3(TT, NB), 256>>>();
    k_out<<<dim3(PP/64, TT, NB), 256>>>(out);
}